// round 1
// baseline (speedup 1.0000x reference)
#include <cuda_runtime.h>
#include <math_constants.h>

#define BB 8
#define NN 2048
#define DIN 256
#define DOUT 128
#define TOPK 16

// Scratch (static device globals — no allocation)
__device__ float g_w2[DIN];
__device__ float g_sj[BB * NN];
__device__ float g_v[BB * DOUT];

// ---------------------------------------------------------------------------
// Kernel A: w2[i] = sum_o W[o,i] * a2[o],  a2 = a[DOUT..2*DOUT)
// 1 block, 256 threads. Coalesced over i.
// ---------------------------------------------------------------------------
__global__ void k_w2(const float* __restrict__ W, const float* __restrict__ a) {
    int i = threadIdx.x;  // 0..255
    float s = 0.f;
#pragma unroll 8
    for (int o = 0; o < DOUT; ++o)
        s += W[o * DIN + i] * a[DOUT + o];
    g_w2[i] = s;
}

// ---------------------------------------------------------------------------
// Kernel B: sj[r] = x[r,:] . w2   for r in [0, B*N)
// One warp per row, 8 warps (256 thr) per block, 2048 blocks. Reads 16 MB.
// ---------------------------------------------------------------------------
__global__ void k_sj(const float* __restrict__ x) {
    __shared__ float w2s[DIN];
    int tid = threadIdx.x;
    w2s[tid] = g_w2[tid];
    __syncthreads();

    int lane = tid & 31;
    int warp = tid >> 5;
    int row  = blockIdx.x * 8 + warp;  // < 16384

    const float4* xr = reinterpret_cast<const float4*>(x + (size_t)row * DIN);
    const float4* w4 = reinterpret_cast<const float4*>(w2s);

    float4 xa = xr[lane];       float4 wa = w4[lane];
    float4 xb = xr[lane + 32];  float4 wb = w4[lane + 32];
    float s = xa.x * wa.x + xa.y * wa.y + xa.z * wa.z + xa.w * wa.w
            + xb.x * wb.x + xb.y * wb.y + xb.z * wb.z + xb.w * wb.w;
#pragma unroll
    for (int o = 16; o; o >>= 1) s += __shfl_xor_sync(0xffffffffu, s, o);
    if (lane == 0) g_sj[row] = s;
}

// ---------------------------------------------------------------------------
// Kernel C: per batch — top-16 of sj (lowest-index tie-break), softmax,
//           xbar = sum_k attn[k]*x[b,idx_k,:],  v = W @ xbar.
// 8 blocks, 256 threads.
// ---------------------------------------------------------------------------
__global__ void k_select(const float* __restrict__ x, const float* __restrict__ W) {
    __shared__ float sv[NN];           // 8 KB
    __shared__ float rmax[8];
    __shared__ int   rarg[8];
    __shared__ float topv[TOPK];
    __shared__ int   topi[TOPK];
    __shared__ float attn[TOPK];
    __shared__ float xbar[DIN];

    int b = blockIdx.x, tid = threadIdx.x;
    int lane = tid & 31, w = tid >> 5;

    for (int j = tid; j < NN; j += 256) sv[j] = g_sj[b * NN + j];
    __syncthreads();

    for (int k = 0; k < TOPK; ++k) {
        float best = -CUDART_INF_F; int bi = NN;
#pragma unroll
        for (int t = 0; t < NN / 256; ++t) {
            int j = tid + t * 256;
            float v = sv[j];
            if (v > best) { best = v; bi = j; }
        }
#pragma unroll
        for (int o = 16; o; o >>= 1) {
            float ov = __shfl_xor_sync(0xffffffffu, best, o);
            int   oi = __shfl_xor_sync(0xffffffffu, bi, o);
            if (ov > best || (ov == best && oi < bi)) { best = ov; bi = oi; }
        }
        if (lane == 0) { rmax[w] = best; rarg[w] = bi; }
        __syncthreads();
        if (tid == 0) {
            float bb = rmax[0]; int ii = rarg[0];
#pragma unroll
            for (int q = 1; q < 8; ++q)
                if (rmax[q] > bb || (rmax[q] == bb && rarg[q] < ii)) { bb = rmax[q]; ii = rarg[q]; }
            topv[k] = bb; topi[k] = ii;
            sv[ii] = -CUDART_INF_F;
        }
        __syncthreads();
    }

    if (tid == 0) {
        float m = topv[0];
#pragma unroll
        for (int k = 1; k < TOPK; ++k) m = fmaxf(m, topv[k]);
        float s = 0.f;
#pragma unroll
        for (int k = 0; k < TOPK; ++k) { float e = expf(topv[k] - m); attn[k] = e; s += e; }
        float inv = 1.f / s;
#pragma unroll
        for (int k = 0; k < TOPK; ++k) attn[k] *= inv;
    }
    __syncthreads();

    // xbar[i] = sum_k attn[k] * x[b, idx_k, i]   (one thread per i)
    {
        float s = 0.f;
#pragma unroll
        for (int k = 0; k < TOPK; ++k)
            s += attn[k] * x[((size_t)b * NN + topi[k]) * DIN + tid];
        xbar[tid] = s;
    }
    __syncthreads();

    // v[d] = W[d,:] . xbar   (one thread per d, d < 128)
    if (tid < DOUT) {
        const float4* wr  = reinterpret_cast<const float4*>(W + tid * DIN);
        const float4* xb4 = reinterpret_cast<const float4*>(xbar);
        float s = 0.f;
#pragma unroll
        for (int q = 0; q < DIN / 4; ++q) {
            float4 wv = wr[q], xv = xb4[q];
            s += wv.x * xv.x + wv.y * xv.y + wv.z * xv.z + wv.w * xv.w;
        }
        g_v[b * DOUT + tid] = s;
    }
}

// ---------------------------------------------------------------------------
// Kernel D: out[b,n,:] = v[b,:]  broadcast. float4 stores, 8 MB.
// ---------------------------------------------------------------------------
__global__ void k_out(float* __restrict__ out) {
    int idx = blockIdx.x * blockDim.x + threadIdx.x;    // over B*N*DOUT/4 = 524288
    const int per_b = NN * DOUT / 4;                    // 65536
    int b  = idx / per_b;
    int d4 = idx & (DOUT / 4 - 1);                      // 32 float4 per row
    float4 v = reinterpret_cast<const float4*>(g_v + b * DOUT)[d4];
    reinterpret_cast<float4*>(out)[idx] = v;
}

// ---------------------------------------------------------------------------
extern "C" void kernel_launch(void* const* d_in, const int* in_sizes, int n_in,
                              void* d_out, int out_size) {
    const float* x = (const float*)d_in[0];   // [8, 2048, 256]
    const float* W = (const float*)d_in[1];   // [128, 256]
    const float* a = (const float*)d_in[2];   // [256]
    float* out = (float*)d_out;               // [8, 2048, 128]

    k_w2<<<1, 256>>>(W, a);
    k_sj<<<BB * NN / 8, 256>>>(x);
    k_select<<<BB, 256>>>(x, W);
    k_out<<<(BB * NN * DOUT / 4) / 256, 256>>>(out);
}

// round 2
// speedup vs baseline: 1.0679x; 1.0679x over previous
#include <cuda_runtime.h>
#include <math_constants.h>

#define BB   8
#define NN   2048
#define DIN  256
#define DOUT 128
#define TOPK 16

// Scratch (static device globals — no allocation)
__device__ float g_sj[BB * NN];
__device__ float g_v[BB * DOUT];
__device__ int   g_flag[BB];

// ---------------------------------------------------------------------------
// K1: fused  w2 = W^T a2  (per-block, redundant, L2-served)  +  sj = x . w2
// grid = 128 blocks (16 per batch), 256 threads; each block: 128 rows.
// Also resets g_flag for this replay (prev K2 has retired — graph is serial).
// ---------------------------------------------------------------------------
__global__ void __launch_bounds__(256) k1_sj(const float* __restrict__ x,
                                             const float* __restrict__ W,
                                             const float* __restrict__ a) {
    __shared__ float a2s[DOUT];
    __shared__ float w2s[DIN];
    int tid = threadIdx.x;

    if (blockIdx.x < BB && tid == 0) g_flag[blockIdx.x] = 0;
    if (tid < DOUT) a2s[tid] = a[DOUT + tid];
    __syncthreads();

    // w2[tid] = sum_o W[o, tid] * a2[o]   (coalesced over tid)
    {
        float s = 0.f;
#pragma unroll 8
        for (int o = 0; o < DOUT; ++o) s += W[o * DIN + tid] * a2s[o];
        w2s[tid] = s;
    }
    __syncthreads();

    int lane = tid & 31, warp = tid >> 5;
    const float4* w4 = reinterpret_cast<const float4*>(w2s);
    float4 wa = w4[lane];
    float4 wb = w4[lane + 32];

    int r0 = blockIdx.x * 128;
#pragma unroll 4
    for (int it = 0; it < 16; ++it) {
        int row = r0 + it * 8 + warp;
        const float4* xr = reinterpret_cast<const float4*>(x + (size_t)row * DIN);
        float4 xa = xr[lane];
        float4 xb = xr[lane + 32];
        float s = xa.x * wa.x + xa.y * wa.y + xa.z * wa.z + xa.w * wa.w
                + xb.x * wb.x + xb.y * wb.y + xb.z * wb.z + xb.w * wb.w;
#pragma unroll
        for (int o = 16; o; o >>= 1) s += __shfl_xor_sync(0xffffffffu, s, o);
        if (lane == 0) g_sj[row] = s;
    }
}

// ---------------------------------------------------------------------------
// K2: blocks 0..7  = per-batch select (top-16, softmax, xbar, v = W @ xbar)
//     blocks 8..519 = output broadcast writers (64 blocks/batch, 32 rows each),
//     spinning on g_flag[b]. Select blocks have the lowest IDs -> scheduled
//     first -> no deadlock regardless of residency.
// ---------------------------------------------------------------------------
__global__ void __launch_bounds__(256) k2_select_out(const float* __restrict__ x,
                                                     const float* __restrict__ W,
                                                     float* __restrict__ out) {
    int tid = threadIdx.x;

    if (blockIdx.x < BB) {
        // ---------------- producer: select ----------------
        __shared__ float wv[8];
        __shared__ int   wj[8];
        __shared__ float topv[TOPK];
        __shared__ int   topi[TOPK];
        __shared__ float attn[TOPK];
        __shared__ float xbar[DIN];

        int b = blockIdx.x;
        int lane = tid & 31, w = tid >> 5;

        // 8 score values per thread, in registers. j = t*256 + tid.
        float vals[8];
#pragma unroll
        for (int t = 0; t < 8; ++t) vals[t] = g_sj[b * NN + t * 256 + tid];

        for (int k = 0; k < TOPK; ++k) {
            float best = vals[0]; int bt = 0;
#pragma unroll
            for (int t = 1; t < 8; ++t)
                if (vals[t] > best) { best = vals[t]; bt = t; }   // strict > keeps lowest j
            int bj = bt * 256 + tid;
#pragma unroll
            for (int o = 16; o; o >>= 1) {
                float ov = __shfl_xor_sync(0xffffffffu, best, o);
                int   oj = __shfl_xor_sync(0xffffffffu, bj, o);
                if (ov > best || (ov == best && oj < bj)) { best = ov; bj = oj; }
            }
            if (lane == 0) { wv[w] = best; wj[w] = bj; }
            __syncthreads();
            if (tid == 0) {
                float bb = wv[0]; int jj = wj[0];
#pragma unroll
                for (int q = 1; q < 8; ++q)
                    if (wv[q] > bb || (wv[q] == bb && wj[q] < jj)) { bb = wv[q]; jj = wj[q]; }
                topv[k] = bb; topi[k] = jj;
            }
            __syncthreads();
            int jj = topi[k];
            if ((jj & 255) == tid) vals[jj >> 8] = -CUDART_INF_F;
        }

        if (tid == 0) {
            float m = topv[0];
#pragma unroll
            for (int k = 1; k < TOPK; ++k) m = fmaxf(m, topv[k]);
            float s = 0.f;
#pragma unroll
            for (int k = 0; k < TOPK; ++k) { float e = expf(topv[k] - m); attn[k] = e; s += e; }
            float inv = 1.f / s;
#pragma unroll
            for (int k = 0; k < TOPK; ++k) attn[k] *= inv;
        }
        __syncthreads();

        // xbar[i] = sum_k attn[k] * x[b, idx_k, i]
        {
            float s = 0.f;
#pragma unroll
            for (int k = 0; k < TOPK; ++k)
                s += attn[k] * x[((size_t)b * NN + topi[k]) * DIN + tid];
            xbar[tid] = s;
        }
        __syncthreads();

        // v[d] = W[d,:] . xbar
        if (tid < DOUT) {
            const float4* wr  = reinterpret_cast<const float4*>(W + tid * DIN);
            const float4* xb4 = reinterpret_cast<const float4*>(xbar);
            float s = 0.f;
#pragma unroll
            for (int q = 0; q < DIN / 4; ++q) {
                float4 wvv = wr[q], xv = xb4[q];
                s += wvv.x * xv.x + wvv.y * xv.y + wvv.z * xv.z + wvv.w * xv.w;
            }
            g_v[b * DOUT + tid] = s;
        }
        __threadfence();
        __syncthreads();
        if (tid == 0) atomicExch(&g_flag[b], 1);

    } else {
        // ---------------- consumer: broadcast write ----------------
        int bid   = blockIdx.x - BB;   // 0..511
        int b     = bid >> 6;          // 64 blocks per batch
        int chunk = bid & 63;          // 32 rows per chunk

        if (tid == 0) {
            volatile int* f = g_flag;
            while (f[b] == 0) {}
            __threadfence();
        }
        __syncthreads();

        float4 v = reinterpret_cast<const float4*>(g_v + b * DOUT)[tid & 31];
        float4* o4 = reinterpret_cast<float4*>(out);
        size_t base = (size_t)b * (NN * DOUT / 4) + (size_t)chunk * 1024;
#pragma unroll
        for (int q = 0; q < 4; ++q)
            o4[base + q * 256 + tid] = v;
    }
}

// ---------------------------------------------------------------------------
extern "C" void kernel_launch(void* const* d_in, const int* in_sizes, int n_in,
                              void* d_out, int out_size) {
    const float* x = (const float*)d_in[0];   // [8, 2048, 256]
    const float* W = (const float*)d_in[1];   // [128, 256]
    const float* a = (const float*)d_in[2];   // [256]
    float* out = (float*)d_out;               // [8, 2048, 128]

    k1_sj<<<128, 256>>>(x, W, a);
    k2_select_out<<<BB + 512, 256>>>(x, W, out);
}

// round 3
// speedup vs baseline: 1.1538x; 1.0805x over previous
#include <cuda_runtime.h>
#include <math_constants.h>

#define BB   8
#define NN   2048
#define DIN  256
#define DOUT 128
#define TOPK 16

__device__ float g_sj[BB * NN];
__device__ float g_v[BB * DOUT];

// ---------------------------------------------------------------------------
// K1: fused  w2 = W^T a2  (per-block redundant, L2-served)  +  sj = x . w2
// 128 blocks x 256 threads; each block handles 128 rows. Streams x (16 MB).
// ---------------------------------------------------------------------------
__global__ void __launch_bounds__(256) k1_sj(const float* __restrict__ x,
                                             const float* __restrict__ W,
                                             const float* __restrict__ a) {
    __shared__ float a2s[DOUT];
    __shared__ float w2s[DIN];
    int tid = threadIdx.x;

    if (tid < DOUT) a2s[tid] = a[DOUT + tid];
    __syncthreads();

    {   // w2[tid] = sum_o W[o, tid] * a2[o]  (block reads W once, 128 KB, L2)
        float s = 0.f;
#pragma unroll 8
        for (int o = 0; o < DOUT; ++o) s += W[o * DIN + tid] * a2s[o];
        w2s[tid] = s;
    }
    __syncthreads();

    int lane = tid & 31, warp = tid >> 5;
    const float4* w4 = reinterpret_cast<const float4*>(w2s);
    float4 wa = w4[lane];
    float4 wb = w4[lane + 32];

    int r0 = blockIdx.x * 128;
#pragma unroll 4
    for (int it = 0; it < 16; ++it) {
        int row = r0 + it * 8 + warp;
        const float4* xr = reinterpret_cast<const float4*>(x + (size_t)row * DIN);
        float4 xa = xr[lane];
        float4 xb = xr[lane + 32];
        float s = xa.x * wa.x + xa.y * wa.y + xa.z * wa.z + xa.w * wa.w
                + xb.x * wb.x + xb.y * wb.y + xb.z * wb.z + xb.w * wb.w;
#pragma unroll
        for (int o = 16; o; o >>= 1) s += __shfl_xor_sync(0xffffffffu, s, o);
        if (lane == 0) g_sj[row] = s;
    }
}

// ---------------------------------------------------------------------------
// K2: per-batch select. 8 blocks x 256 threads.
//   Phase 1: each warp finds top-16 of its 256 scores (registers + shuffles,
//            NO block syncs).
//   Phase 2: rank-count merge of the 128 candidates (fully parallel); the
//            top-16 SET is enough — softmax & the weighted sum are
//            order-invariant.
//   Phase 3: warp-parallel softmax, gather xbar, v = W @ xbar.
// ---------------------------------------------------------------------------
__global__ void __launch_bounds__(256) k2_select(const float* __restrict__ x,
                                                 const float* __restrict__ W) {
    __shared__ float cand_v[128];
    __shared__ int   cand_j[128];
    __shared__ float sel_v[TOPK];
    __shared__ int   sel_j[TOPK];
    __shared__ float attn[TOPK];
    __shared__ float xbar[DIN];

    int b = blockIdx.x, tid = threadIdx.x;
    int lane = tid & 31, w = tid >> 5;

    // ---- Phase 1: per-warp top-16 (values in registers) ----
    float v[8];
    int base = b * NN + w * 256;
#pragma unroll
    for (int t = 0; t < 8; ++t) v[t] = g_sj[base + t * 32 + lane];

#pragma unroll 1
    for (int k = 0; k < TOPK; ++k) {
        float bv = v[0]; int bt = 0;
#pragma unroll
        for (int t = 1; t < 8; ++t)
            if (v[t] > bv) { bv = v[t]; bt = t; }
        int bj = bt * 32 + lane;            // index within this warp's 256
#pragma unroll
        for (int o = 16; o; o >>= 1) {
            float ov = __shfl_xor_sync(0xffffffffu, bv, o);
            int   oj = __shfl_xor_sync(0xffffffffu, bj, o);
            if (ov > bv) { bv = ov; bj = oj; }
        }
        if (lane == (bj & 31)) v[bj >> 5] = -CUDART_INF_F;   // owner clears
        if (lane == 0) { cand_v[w * TOPK + k] = bv; cand_j[w * TOPK + k] = w * 256 + bj; }
    }
    __syncthreads();

    // ---- Phase 2: parallel rank-count over 128 candidates ----
    if (tid < 128) {
        float mv = cand_v[tid];
        int   mj = cand_j[tid];
        int rank = 0;
#pragma unroll 8
        for (int c = 0; c < 128; ++c) rank += (cand_v[c] > mv);
        if (rank < TOPK) { sel_v[rank] = mv; sel_j[rank] = mj; }
    }
    __syncthreads();

    // ---- Phase 3a: warp-parallel softmax over the 16 selected ----
    if (tid < TOPK) {
        float val = sel_v[tid];
        float m = val;
#pragma unroll
        for (int o = 8; o; o >>= 1) m = fmaxf(m, __shfl_xor_sync(0xffffu, m, o));
        float e = expf(val - m);
        float s = e;
#pragma unroll
        for (int o = 8; o; o >>= 1) s += __shfl_xor_sync(0xffffu, s, o);
        attn[tid] = e / s;
    }
    __syncthreads();

    // ---- Phase 3b: xbar[i] = sum_k attn[k] * x[b, sel_j[k], i] ----
    {
        float s = 0.f;
#pragma unroll
        for (int k = 0; k < TOPK; ++k)
            s += attn[k] * x[((size_t)b * NN + sel_j[k]) * DIN + tid];
        xbar[tid] = s;
    }
    __syncthreads();

    // ---- Phase 3c: v[d] = W[d,:] . xbar ----
    if (tid < DOUT) {
        const float4* wr  = reinterpret_cast<const float4*>(W + tid * DIN);
        const float4* xb4 = reinterpret_cast<const float4*>(xbar);
        float s = 0.f;
#pragma unroll
        for (int q = 0; q < DIN / 4; ++q) {
            float4 wv = wr[q], xv = xb4[q];
            s += wv.x * xv.x + wv.y * xv.y + wv.z * xv.z + wv.w * xv.w;
        }
        g_v[b * DOUT + tid] = s;
    }
}

// ---------------------------------------------------------------------------
// K3: out[b,n,:] = v[b,:]  broadcast. 256 blocks x 256 threads,
// 8 float4 stores per thread (2 MB/block-row, fully coalesced).
// ---------------------------------------------------------------------------
__global__ void __launch_bounds__(256) k3_out(float* __restrict__ out) {
    int blk = blockIdx.x;            // 0..255
    int b     = blk >> 5;            // 32 blocks per batch
    int chunk = blk & 31;            // 64 rows per block
    int tid = threadIdx.x;

    float4 v = reinterpret_cast<const float4*>(g_v + b * DOUT)[tid & 31];
    float4* o4 = reinterpret_cast<float4*>(out);
    size_t base = (size_t)b * (NN * DOUT / 4) + (size_t)chunk * 2048;
#pragma unroll
    for (int q = 0; q < 8; ++q)
        o4[base + q * 256 + tid] = v;
}

// ---------------------------------------------------------------------------
extern "C" void kernel_launch(void* const* d_in, const int* in_sizes, int n_in,
                              void* d_out, int out_size) {
    const float* x = (const float*)d_in[0];   // [8, 2048, 256]
    const float* W = (const float*)d_in[1];   // [128, 256]
    const float* a = (const float*)d_in[2];   // [256]
    float* out = (float*)d_out;               // [8, 2048, 128]

    k1_sj<<<128, 256>>>(x, W, a);
    k2_select<<<BB, 256>>>(x, W);
    k3_out<<<256, 256>>>(out);
}

// round 4
// speedup vs baseline: 1.3483x; 1.1685x over previous
#include <cuda_runtime.h>
#include <math_constants.h>

#define BB   8
#define NN   2048
#define DIN  256
#define DOUT 128
#define TOPK 16

__device__ float g_w2p[4 * DIN];   // 4 partial w2 vectors
__device__ float g_sj[BB * NN];
__device__ float g_v[BB * DOUT];

// ---------------------------------------------------------------------------
// K0: partial w2.  Block p computes sum over o in [32p, 32p+32):
//     g_w2p[p*256 + i] = sum_o W[o,i] * a[DOUT+o].   4 blocks x 256 threads.
// ---------------------------------------------------------------------------
__global__ void __launch_bounds__(256) k0_w2(const float* __restrict__ W,
                                             const float* __restrict__ a) {
    int i = threadIdx.x;
    int o0 = blockIdx.x * 32;
    float s = 0.f;
#pragma unroll
    for (int q = 0; q < 32; ++q)
        s += W[(o0 + q) * DIN + i] * __ldg(a + DOUT + o0 + q);
    g_w2p[blockIdx.x * DIN + i] = s;
}

// ---------------------------------------------------------------------------
// K1: sj[r] = x[r,:] . w2.   512 blocks x 256 threads; each warp does exactly
// 4 rows with all 8 float4 loads issued up front (MLP=8/thread), and the four
// shuffle reductions interleaved. No loop, one latency wave.
// ---------------------------------------------------------------------------
__global__ void __launch_bounds__(256) k1_sj(const float* __restrict__ x) {
    __shared__ float w2s[DIN];
    int tid = threadIdx.x;
    w2s[tid] = g_w2p[tid] + g_w2p[DIN + tid] + g_w2p[2 * DIN + tid] + g_w2p[3 * DIN + tid];
    __syncthreads();

    int lane = tid & 31, warp = tid >> 5;
    int r0 = blockIdx.x * 32 + warp * 4;          // 4 consecutive rows per warp

    const float4* x4 = reinterpret_cast<const float4*>(x);
    size_t base = (size_t)r0 * (DIN / 4);         // float4 units; 64 per row

    // Front-load all 8 loads (2 per row x 4 rows)
    float4 a0 = x4[base            + lane];
    float4 b0 = x4[base            + lane + 32];
    float4 a1 = x4[base + 64       + lane];
    float4 b1 = x4[base + 64       + lane + 32];
    float4 a2 = x4[base + 128      + lane];
    float4 b2 = x4[base + 128      + lane + 32];
    float4 a3 = x4[base + 192      + lane];
    float4 b3 = x4[base + 192      + lane + 32];

    const float4* w4 = reinterpret_cast<const float4*>(w2s);
    float4 wa = w4[lane];
    float4 wb = w4[lane + 32];

    float s0 = a0.x*wa.x + a0.y*wa.y + a0.z*wa.z + a0.w*wa.w
             + b0.x*wb.x + b0.y*wb.y + b0.z*wb.z + b0.w*wb.w;
    float s1 = a1.x*wa.x + a1.y*wa.y + a1.z*wa.z + a1.w*wa.w
             + b1.x*wb.x + b1.y*wb.y + b1.z*wb.z + b1.w*wb.w;
    float s2 = a2.x*wa.x + a2.y*wa.y + a2.z*wa.z + a2.w*wa.w
             + b2.x*wb.x + b2.y*wb.y + b2.z*wb.z + b2.w*wb.w;
    float s3 = a3.x*wa.x + a3.y*wa.y + a3.z*wa.z + a3.w*wa.w
             + b3.x*wb.x + b3.y*wb.y + b3.z*wb.z + b3.w*wb.w;

    // Interleaved xor-reductions (4 independent chains -> ILP)
#pragma unroll
    for (int o = 16; o; o >>= 1) {
        s0 += __shfl_xor_sync(0xffffffffu, s0, o);
        s1 += __shfl_xor_sync(0xffffffffu, s1, o);
        s2 += __shfl_xor_sync(0xffffffffu, s2, o);
        s3 += __shfl_xor_sync(0xffffffffu, s3, o);
    }
    if (lane < 4) {
        float s = (lane == 0) ? s0 : (lane == 1) ? s1 : (lane == 2) ? s2 : s3;
        g_sj[r0 + lane] = s;
    }
}

// ---------------------------------------------------------------------------
// K2: per-batch select (8 blocks x 256 thr). Warp-local top-16 in registers,
// parallel rank-count merge (top-16 SET suffices: softmax+sum are
// order-invariant), warp softmax, gather xbar, v = W @ xbar.
// ---------------------------------------------------------------------------
__global__ void __launch_bounds__(256) k2_select(const float* __restrict__ x,
                                                 const float* __restrict__ W) {
    __shared__ float cand_v[128];
    __shared__ int   cand_j[128];
    __shared__ float sel_v[TOPK];
    __shared__ int   sel_j[TOPK];
    __shared__ float attn[TOPK];
    __shared__ float xbar[DIN];

    int b = blockIdx.x, tid = threadIdx.x;
    int lane = tid & 31, w = tid >> 5;

    float v[8];
    int base = b * NN + w * 256;
#pragma unroll
    for (int t = 0; t < 8; ++t) v[t] = g_sj[base + t * 32 + lane];

#pragma unroll 1
    for (int k = 0; k < TOPK; ++k) {
        float bv = v[0]; int bt = 0;
#pragma unroll
        for (int t = 1; t < 8; ++t)
            if (v[t] > bv) { bv = v[t]; bt = t; }
        int bj = bt * 32 + lane;
#pragma unroll
        for (int o = 16; o; o >>= 1) {
            float ov = __shfl_xor_sync(0xffffffffu, bv, o);
            int   oj = __shfl_xor_sync(0xffffffffu, bj, o);
            if (ov > bv) { bv = ov; bj = oj; }
        }
        if (lane == (bj & 31)) v[bj >> 5] = -CUDART_INF_F;
        if (lane == 0) { cand_v[w * TOPK + k] = bv; cand_j[w * TOPK + k] = w * 256 + bj; }
    }
    __syncthreads();

    if (tid < 128) {
        float mv = cand_v[tid];
        int   mj = cand_j[tid];
        int rank = 0;
#pragma unroll 8
        for (int c = 0; c < 128; ++c) rank += (cand_v[c] > mv);
        if (rank < TOPK) { sel_v[rank] = mv; sel_j[rank] = mj; }
    }
    __syncthreads();

    if (tid < TOPK) {
        float val = sel_v[tid];
        float m = val;
#pragma unroll
        for (int o = 8; o; o >>= 1) m = fmaxf(m, __shfl_xor_sync(0xffffu, m, o));
        float e = expf(val - m);
        float s = e;
#pragma unroll
        for (int o = 8; o; o >>= 1) s += __shfl_xor_sync(0xffffu, s, o);
        attn[tid] = e / s;
    }
    __syncthreads();

    {
        float s = 0.f;
#pragma unroll
        for (int k = 0; k < TOPK; ++k)
            s += attn[k] * x[((size_t)b * NN + sel_j[k]) * DIN + tid];
        xbar[tid] = s;
    }
    __syncthreads();

    if (tid < DOUT) {
        const float4* wr  = reinterpret_cast<const float4*>(W + tid * DIN);
        const float4* xb4 = reinterpret_cast<const float4*>(xbar);
        float s = 0.f;
#pragma unroll
        for (int q = 0; q < DIN / 4; ++q) {
            float4 wv = wr[q], xv = xb4[q];
            s += wv.x * xv.x + wv.y * xv.y + wv.z * xv.z + wv.w * xv.w;
        }
        g_v[b * DOUT + tid] = s;
    }
}

// ---------------------------------------------------------------------------
// K3: out[b,n,:] = v[b,:] broadcast. 256 blocks x 256 threads,
// 8 float4 stores per thread, fully coalesced.
// ---------------------------------------------------------------------------
__global__ void __launch_bounds__(256) k3_out(float* __restrict__ out) {
    int blk = blockIdx.x;
    int b     = blk >> 5;
    int chunk = blk & 31;
    int tid = threadIdx.x;

    float4 v = reinterpret_cast<const float4*>(g_v + b * DOUT)[tid & 31];
    float4* o4 = reinterpret_cast<float4*>(out);
    size_t base = (size_t)b * (NN * DOUT / 4) + (size_t)chunk * 2048;
#pragma unroll
    for (int q = 0; q < 8; ++q)
        o4[base + q * 256 + tid] = v;
}

// ---------------------------------------------------------------------------
extern "C" void kernel_launch(void* const* d_in, const int* in_sizes, int n_in,
                              void* d_out, int out_size) {
    const float* x = (const float*)d_in[0];   // [8, 2048, 256]
    const float* W = (const float*)d_in[1];   // [128, 256]
    const float* a = (const float*)d_in[2];   // [256]
    float* out = (float*)d_out;               // [8, 2048, 128]

    k0_w2<<<4, 256>>>(W, a);
    k1_sj<<<512, 256>>>(x);
    k2_select<<<BB, 256>>>(x, W);
    k3_out<<<256, 256>>>(out);
}

// round 5
// speedup vs baseline: 1.3636x; 1.0114x over previous
#include <cuda_runtime.h>
#include <math_constants.h>

#define BB   8
#define NN   2048
#define DIN  256
#define DOUT 128
#define TOPK 16

__device__ float g_w2p[4 * DIN];   // 4 partial w2 vectors
__device__ float g_sj[BB * NN];
__device__ float g_v[BB * DOUT];

// ---------------------------------------------------------------------------
// K0: partial w2.  Block p: g_w2p[p*256+i] = sum_{o in [32p,32p+32)} W[o,i]*a2[o]
// ---------------------------------------------------------------------------
__global__ void __launch_bounds__(256) k0_w2(const float* __restrict__ W,
                                             const float* __restrict__ a) {
    cudaTriggerProgrammaticLaunchCompletion();
    int i = threadIdx.x;
    int o0 = blockIdx.x * 32;
    float s = 0.f;
#pragma unroll
    for (int q = 0; q < 32; ++q)
        s += W[(o0 + q) * DIN + i] * __ldg(a + DOUT + o0 + q);
    g_w2p[blockIdx.x * DIN + i] = s;
}

// ---------------------------------------------------------------------------
// K1: sj[r] = x[r,:] . w2.  512 blocks x 256 thr; warp = 4 rows, 8 float4
// loads front-issued BEFORE the PDL grid sync (they don't depend on k0).
// ---------------------------------------------------------------------------
__global__ void __launch_bounds__(256) k1_sj(const float* __restrict__ x) {
    cudaTriggerProgrammaticLaunchCompletion();
    __shared__ float w2s[DIN];
    int tid = threadIdx.x;
    int lane = tid & 31, warp = tid >> 5;
    int r0 = blockIdx.x * 32 + warp * 4;

    const float4* x4 = reinterpret_cast<const float4*>(x);
    size_t base = (size_t)r0 * (DIN / 4);

    // Independent of k0 — issue while k0 may still be running.
    float4 a0 = x4[base        + lane];
    float4 b0 = x4[base        + lane + 32];
    float4 a1 = x4[base + 64   + lane];
    float4 b1 = x4[base + 64   + lane + 32];
    float4 a2 = x4[base + 128  + lane];
    float4 b2 = x4[base + 128  + lane + 32];
    float4 a3 = x4[base + 192  + lane];
    float4 b3 = x4[base + 192  + lane + 32];

    cudaGridDependencySynchronize();   // k0's g_w2p now visible

    w2s[tid] = g_w2p[tid] + g_w2p[DIN + tid] + g_w2p[2 * DIN + tid] + g_w2p[3 * DIN + tid];
    __syncthreads();

    const float4* w4 = reinterpret_cast<const float4*>(w2s);
    float4 wa = w4[lane];
    float4 wb = w4[lane + 32];

    float s0 = a0.x*wa.x + a0.y*wa.y + a0.z*wa.z + a0.w*wa.w
             + b0.x*wb.x + b0.y*wb.y + b0.z*wb.z + b0.w*wb.w;
    float s1 = a1.x*wa.x + a1.y*wa.y + a1.z*wa.z + a1.w*wa.w
             + b1.x*wb.x + b1.y*wb.y + b1.z*wb.z + b1.w*wb.w;
    float s2 = a2.x*wa.x + a2.y*wa.y + a2.z*wa.z + a2.w*wa.w
             + b2.x*wb.x + b2.y*wb.y + b2.z*wb.z + b2.w*wb.w;
    float s3 = a3.x*wa.x + a3.y*wa.y + a3.z*wa.z + a3.w*wa.w
             + b3.x*wb.x + b3.y*wb.y + b3.z*wb.z + b3.w*wb.w;

#pragma unroll
    for (int o = 16; o; o >>= 1) {
        s0 += __shfl_xor_sync(0xffffffffu, s0, o);
        s1 += __shfl_xor_sync(0xffffffffu, s1, o);
        s2 += __shfl_xor_sync(0xffffffffu, s2, o);
        s3 += __shfl_xor_sync(0xffffffffu, s3, o);
    }
    if (lane < 4) {
        float s = (lane == 0) ? s0 : (lane == 1) ? s1 : (lane == 2) ? s2 : s3;
        g_sj[r0 + lane] = s;
    }
}

// ---------------------------------------------------------------------------
// K2: per-batch select (8 blocks x 256 thr). Warp-local top-16 in registers,
// parallel rank-count merge (the top-16 SET suffices), warp softmax, gather
// xbar, v = W @ xbar.
// ---------------------------------------------------------------------------
__global__ void __launch_bounds__(256) k2_select(const float* __restrict__ x,
                                                 const float* __restrict__ W) {
    cudaTriggerProgrammaticLaunchCompletion();
    __shared__ float cand_v[128];
    __shared__ int   cand_j[128];
    __shared__ float sel_v[TOPK];
    __shared__ int   sel_j[TOPK];
    __shared__ float attn[TOPK];
    __shared__ float xbar[DIN];

    int b = blockIdx.x, tid = threadIdx.x;
    int lane = tid & 31, w = tid >> 5;

    cudaGridDependencySynchronize();   // k1's g_sj now visible

    float v[8];
    int base = b * NN + w * 256;
#pragma unroll
    for (int t = 0; t < 8; ++t) v[t] = g_sj[base + t * 32 + lane];

#pragma unroll 1
    for (int k = 0; k < TOPK; ++k) {
        float bv = v[0]; int bt = 0;
#pragma unroll
        for (int t = 1; t < 8; ++t)
            if (v[t] > bv) { bv = v[t]; bt = t; }
        int bj = bt * 32 + lane;
#pragma unroll
        for (int o = 16; o; o >>= 1) {
            float ov = __shfl_xor_sync(0xffffffffu, bv, o);
            int   oj = __shfl_xor_sync(0xffffffffu, bj, o);
            if (ov > bv) { bv = ov; bj = oj; }
        }
        if (lane == (bj & 31)) v[bj >> 5] = -CUDART_INF_F;
        if (lane == 0) { cand_v[w * TOPK + k] = bv; cand_j[w * TOPK + k] = w * 256 + bj; }
    }
    __syncthreads();

    if (tid < 128) {
        float mv = cand_v[tid];
        int   mj = cand_j[tid];
        int rank = 0;
#pragma unroll 8
        for (int c = 0; c < 128; ++c) rank += (cand_v[c] > mv);
        if (rank < TOPK) { sel_v[rank] = mv; sel_j[rank] = mj; }
    }
    __syncthreads();

    if (tid < TOPK) {
        float val = sel_v[tid];
        float m = val;
#pragma unroll
        for (int o = 8; o; o >>= 1) m = fmaxf(m, __shfl_xor_sync(0xffffu, m, o));
        float e = expf(val - m);
        float s = e;
#pragma unroll
        for (int o = 8; o; o >>= 1) s += __shfl_xor_sync(0xffffu, s, o);
        attn[tid] = e / s;
    }
    __syncthreads();

    {
        float s = 0.f;
#pragma unroll
        for (int k = 0; k < TOPK; ++k)
            s += attn[k] * x[((size_t)b * NN + sel_j[k]) * DIN + tid];
        xbar[tid] = s;
    }
    __syncthreads();

    if (tid < DOUT) {
        const float4* wr  = reinterpret_cast<const float4*>(W + tid * DIN);
        const float4* xb4 = reinterpret_cast<const float4*>(xbar);
        float s = 0.f;
#pragma unroll
        for (int q = 0; q < DIN / 4; ++q) {
            float4 wv = wr[q], xv = xb4[q];
            s += wv.x * xv.x + wv.y * xv.y + wv.z * xv.z + wv.w * xv.w;
        }
        g_v[b * DOUT + tid] = s;
    }
}

// ---------------------------------------------------------------------------
// K3: out[b,n,:] = v[b,:] broadcast. 512 blocks x 256 thr, 4 float4 stores
// per thread. Launches during k2 (PDL); syncs before reading g_v.
// ---------------------------------------------------------------------------
__global__ void __launch_bounds__(256) k3_out(float* __restrict__ out) {
    int blk = blockIdx.x;            // 0..511
    int b     = blk >> 6;            // 64 blocks per batch
    int chunk = blk & 63;            // 32 rows per block
    int tid = threadIdx.x;

    cudaGridDependencySynchronize();  // k2's g_v now visible

    float4 v = reinterpret_cast<const float4*>(g_v + b * DOUT)[tid & 31];
    float4* o4 = reinterpret_cast<float4*>(out);
    size_t base = (size_t)b * (NN * DOUT / 4) + (size_t)chunk * 1024;
#pragma unroll
    for (int q = 0; q < 4; ++q)
        o4[base + q * 256 + tid] = v;
}

// ---------------------------------------------------------------------------
extern "C" void kernel_launch(void* const* d_in, const int* in_sizes, int n_in,
                              void* d_out, int out_size) {
    const float* x = (const float*)d_in[0];   // [8, 2048, 256]
    const float* W = (const float*)d_in[1];   // [128, 256]
    const float* a = (const float*)d_in[2];   // [256]
    float* out = (float*)d_out;               // [8, 2048, 128]

    cudaLaunchAttribute attr[1];
    attr[0].id = cudaLaunchAttributeProgrammaticStreamSerialization;
    attr[0].val.programmaticStreamSerializationAllowed = 1;

    cudaLaunchConfig_t cfg = {};
    cfg.blockDim = {256, 1, 1};
    cfg.attrs = attr;
    cfg.numAttrs = 1;

    cfg.gridDim = {4, 1, 1};
    cudaLaunchKernelEx(&cfg, k0_w2, W, a);

    cfg.gridDim = {512, 1, 1};
    cudaLaunchKernelEx(&cfg, k1_sj, x);

    cfg.gridDim = {BB, 1, 1};
    cudaLaunchKernelEx(&cfg, k2_select, x, W);

    cfg.gridDim = {512, 1, 1};
    cudaLaunchKernelEx(&cfg, k3_out, out);
}